// round 3
// baseline (speedup 1.0000x reference)
#include <cuda_runtime.h>
#include <cmath>

#define DINL __device__ __forceinline__
#define NPOS  32768
#define NYTOT 2097152
#define NY4   524288
#define NH1P  4460544
#define NH1P4 1115136

// ---- device state ----
__device__ float g_y[NYTOT];
__device__ float g_y5[NYTOT];
__device__ float g_k[7][NYTOT];
__device__ float g_h1p[NH1P];          // [8][66][66][128] zero-padded
__device__ float g_h2[NPOS*128];
__device__ float g_red[512];
__device__ float g_t, g_h, g_hs, g_ts[7];
__device__ int   g_done, g_accept;

__constant__ float c_A[7][5] = {
  {0,0,0,0,0},
  {0.2f,0,0,0,0},
  {(float)(3.0/40.0),(float)(9.0/40.0),0,0,0},
  {(float)(44.0/45.0),(float)(-56.0/15.0),(float)(32.0/9.0),0,0},
  {(float)(19372.0/6561.0),(float)(-25360.0/2187.0),(float)(64448.0/6561.0),(float)(-212.0/729.0),0},
  {(float)(9017.0/3168.0),(float)(-355.0/33.0),(float)(46732.0/5247.0),(float)(49.0/176.0),(float)(-5103.0/18656.0)},
  {0,0,0,0,0}
};
static __device__ __constant__ float B1f=(float)(35.0/384.0), B3f=(float)(500.0/1113.0),
  B4f=(float)(125.0/192.0), B5f=(float)(-2187.0/6784.0), B6f=(float)(11.0/84.0);
static __device__ __constant__ float E1f=(float)(71.0/57600.0), E3f=(float)(-71.0/16695.0),
  E4f=(float)(71.0/1920.0), E5f=(float)(-17253.0/339200.0), E6f=(float)(22.0/525.0), E7f=(float)(-1.0/40.0);

DINL float4 ld4(const float* p){ return *reinterpret_cast<const float4*>(p); }
DINL void   st4(float* p, float4 v){ *reinterpret_cast<float4*>(p) = v; }

// ---- small kernels ----
__global__ void k_init(){ g_t=0.f; g_h=0.1f; g_done=0; g_accept=0; }

__global__ void k_copyx(const float* __restrict__ x){
  int i = blockIdx.x*blockDim.x + threadIdx.x;
  reinterpret_cast<float4*>(g_y)[i] = reinterpret_cast<const float4*>(x)[i];
}

__global__ void k_zero_h1p(){
  float4 z; z.x=z.y=z.z=z.w=0.f;
  for (int i = blockIdx.x*blockDim.x + threadIdx.x; i < NH1P4; i += gridDim.x*blockDim.x)
    reinterpret_cast<float4*>(g_h1p)[i] = z;
}

__global__ void k_hs(){
  float t=g_t, h=g_h;
  g_done = (t >= 1.0f);
  float hs = fminf(h, 1.0f - t);
  g_hs = hs;
  g_ts[0]=t; g_ts[1]=t+hs*0.2f; g_ts[2]=t+hs*0.3f; g_ts[3]=t+hs*0.8f;
  g_ts[4]=t+hs*(float)(8.0/9.0); g_ts[5]=t+hs; g_ts[6]=t+hs;
}

// ---- conv1: [32768,64]x[64,128] + stage combine + time-bias + relu -> padded h1 ----
__global__ __launch_bounds__(256) void k_conv1(const float* __restrict__ w1,
                                               const float* __restrict__ b1,
                                               int stage, int useY5){
  if (g_done) return;
  __shared__ float As[16][136];
  __shared__ float Bs[16][128];
  const float hs = g_hs, tv = g_ts[stage];
  const int cnt = (stage>=1 && stage<=5) ? stage : 0;
  float e[5];
  #pragma unroll
  for (int j=0;j<5;j++) e[j] = hs * c_A[stage][j];
  const float* base = useY5 ? g_y5 : g_y;
  const int m0 = blockIdx.x*128, tid = threadIdx.x;
  const int lr = tid>>2, lc = (tid&3)<<2;
  const int kr = tid>>4, cg = (tid&15)<<3;
  const int ty = tid>>4, tx = tid&15;

  float acc[8][8];
  #pragma unroll
  for (int i=0;i<8;i++){
    #pragma unroll
    for (int j=0;j<8;j++) acc[i][j]=0.f;
  }

  for (int k0=0;k0<64;k0+=16){
    #pragma unroll
    for (int rr=0;rr<2;rr++){
      int r = lr + rr*64;
      int gi = (m0+r)*64 + k0 + lc;
      float4 v = ld4(base+gi);
      #pragma unroll
      for (int j=0;j<5;j++){
        if (j < cnt){
          float4 u = ld4(&g_k[j][gi]);
          v.x=fmaf(e[j],u.x,v.x); v.y=fmaf(e[j],u.y,v.y);
          v.z=fmaf(e[j],u.z,v.z); v.w=fmaf(e[j],u.w,v.w);
        }
      }
      As[lc+0][r]=v.x; As[lc+1][r]=v.y; As[lc+2][r]=v.z; As[lc+3][r]=v.w;
    }
    const float* bp = w1 + (1 + k0 + kr)*128 + cg;   // skip time row 0
    st4(&Bs[kr][cg], ld4(bp)); st4(&Bs[kr][cg+4], ld4(bp+4));
    __syncthreads();
    #pragma unroll
    for (int kk=0;kk<16;kk++){
      float4 x0=ld4(&As[kk][ty*8]), x1=ld4(&As[kk][ty*8+4]);
      float4 z0=ld4(&Bs[kk][tx*8]), z1=ld4(&Bs[kk][tx*8+4]);
      float av[8]={x0.x,x0.y,x0.z,x0.w,x1.x,x1.y,x1.z,x1.w};
      float bv[8]={z0.x,z0.y,z0.z,z0.w,z1.x,z1.y,z1.z,z1.w};
      #pragma unroll
      for (int i=0;i<8;i++){
        #pragma unroll
        for (int j=0;j<8;j++) acc[i][j]=fmaf(av[i],bv[j],acc[i][j]);
      }
    }
    __syncthreads();
  }
  float be[8];
  #pragma unroll
  for (int j=0;j<8;j++){ int n=tx*8+j; be[j]=b1[n]+tv*w1[n]; }
  #pragma unroll
  for (int i=0;i<8;i++){
    int m=m0+ty*8+i;
    int bb=m>>12, yy=(m>>6)&63, xx=m&63;
    float* dst = g_h1p + (((bb*66)+(yy+1))*66+(xx+1))*128 + tx*8;
    float4 o0,o1;
    o0.x=fmaxf(acc[i][0]+be[0],0.f); o0.y=fmaxf(acc[i][1]+be[1],0.f);
    o0.z=fmaxf(acc[i][2]+be[2],0.f); o0.w=fmaxf(acc[i][3]+be[3],0.f);
    o1.x=fmaxf(acc[i][4]+be[4],0.f); o1.y=fmaxf(acc[i][5]+be[5],0.f);
    o1.z=fmaxf(acc[i][6]+be[6],0.f); o1.w=fmaxf(acc[i][7]+be[7],0.f);
    st4(dst,o0); st4(dst+4,o1);
  }
}

// ---- conv2: implicit 3x3 GEMM [32768,1152]x[1152,128] + time-mask bias + relu ----
__global__ __launch_bounds__(256,2) void k_conv2(const float* __restrict__ w2,
                                                 const float* __restrict__ b2,
                                                 int stage){
  if (g_done) return;
  __shared__ float As[2][16][136];
  __shared__ float Bs[2][16][128];
  const float tv = g_ts[stage];
  const int m0 = blockIdx.x*128, tid = threadIdx.x;
  const int lr = tid>>2, lc = (tid&3)<<2;
  const int kr = tid>>4, cg = (tid&15)<<3;
  const int ty = tid>>4, tx = tid&15;
  const int bb = m0>>12;
  const int mr0 = m0+lr, mr1 = mr0+64;
  const int base0 = ((bb*66 + (((mr0>>6)&63)+1))*66 + ((mr0&63)+1))*128;
  const int base1 = ((bb*66 + (((mr1>>6)&63)+1))*66 + ((mr1&63)+1))*128;

  float acc[8][8];
  #pragma unroll
  for (int i=0;i<8;i++){
    #pragma unroll
    for (int j=0;j<8;j++) acc[i][j]=0.f;
  }

  float4 a0v,a1v,b0v,b1v;
#define LOADC(KC) { int tap_=(KC)>>3, ci0_=((KC)&7)<<4; \
    int dy_=tap_/3, dx_=tap_-dy_*3; \
    int off_=((dy_-1)*66+(dx_-1))*128 + ci0_ + lc; \
    a0v=ld4(g_h1p+base0+off_); a1v=ld4(g_h1p+base1+off_); \
    const float* bp_=w2+(tap_*129+1+ci0_+kr)*128+cg; \
    b0v=ld4(bp_); b1v=ld4(bp_+4); }
#define STOREC(BUF) { \
    As[BUF][lc+0][lr]=a0v.x; As[BUF][lc+1][lr]=a0v.y; As[BUF][lc+2][lr]=a0v.z; As[BUF][lc+3][lr]=a0v.w; \
    As[BUF][lc+0][lr+64]=a1v.x; As[BUF][lc+1][lr+64]=a1v.y; As[BUF][lc+2][lr+64]=a1v.z; As[BUF][lc+3][lr+64]=a1v.w; \
    st4(&Bs[BUF][kr][cg],b0v); st4(&Bs[BUF][kr][cg+4],b1v); }

  LOADC(0); STOREC(0); __syncthreads();
  for (int kc=0;kc<72;kc++){
    int cur = kc&1;
    if (kc<71) LOADC(kc+1);
    #pragma unroll
    for (int kk=0;kk<16;kk++){
      float4 x0=ld4(&As[cur][kk][ty*8]), x1=ld4(&As[cur][kk][ty*8+4]);
      float4 z0=ld4(&Bs[cur][kk][tx*8]), z1=ld4(&Bs[cur][kk][tx*8+4]);
      float av[8]={x0.x,x0.y,x0.z,x0.w,x1.x,x1.y,x1.z,x1.w};
      float bv[8]={z0.x,z0.y,z0.z,z0.w,z1.x,z1.y,z1.z,z1.w};
      #pragma unroll
      for (int i=0;i<8;i++){
        #pragma unroll
        for (int j=0;j<8;j++) acc[i][j]=fmaf(av[i],bv[j],acc[i][j]);
      }
    }
    __syncthreads();
    if (kc<71){ STOREC((kc&1)^1); __syncthreads(); }
  }
#undef LOADC
#undef STOREC
  // epilogue: time-row of each tap, with border validity mask
  float* w2ts = &As[0][0][0];             // 1152 floats
  for (int i=tid;i<1152;i+=256){ int tap=i>>7, f=i&127; w2ts[i]=w2[(tap*129)*128+f]; }
  __syncthreads();
  float be[8];
  #pragma unroll
  for (int j=0;j<8;j++) be[j]=b2[tx*8+j];
  #pragma unroll
  for (int i=0;i<8;i++){
    int m=m0+ty*8+i;
    int yy=(m>>6)&63, xx=m&63;
    float tb[8]={0,0,0,0,0,0,0,0};
    #pragma unroll
    for (int tyy=0;tyy<3;tyy++){
      bool vy = (tyy==0)?(yy>0):((tyy==2)?(yy<63):true);
      #pragma unroll
      for (int txx=0;txx<3;txx++){
        bool vx = (txx==0)?(xx>0):((txx==2)?(xx<63):true);
        if (vy&&vx){
          int tap=tyy*3+txx;
          #pragma unroll
          for (int j=0;j<8;j++) tb[j]+=w2ts[tap*128+tx*8+j];
        }
      }
    }
    float4 o0,o1;
    o0.x=fmaxf(acc[i][0]+be[0]+tv*tb[0],0.f); o0.y=fmaxf(acc[i][1]+be[1]+tv*tb[1],0.f);
    o0.z=fmaxf(acc[i][2]+be[2]+tv*tb[2],0.f); o0.w=fmaxf(acc[i][3]+be[3]+tv*tb[3],0.f);
    o1.x=fmaxf(acc[i][4]+be[4]+tv*tb[4],0.f); o1.y=fmaxf(acc[i][5]+be[5]+tv*tb[5],0.f);
    o1.z=fmaxf(acc[i][6]+be[6]+tv*tb[6],0.f); o1.w=fmaxf(acc[i][7]+be[7]+tv*tb[7],0.f);
    st4(g_h2+m*128+tx*8,o0); st4(g_h2+m*128+tx*8+4,o1);
  }
}

// ---- conv3: [32768,128]x[128,64] + time-bias -> g_k[stageOut] ----
__global__ __launch_bounds__(256) void k_conv3(const float* __restrict__ w3,
                                               const float* __restrict__ b3,
                                               int stage, int stageOut){
  if (g_done) return;
  __shared__ float As[16][136];
  __shared__ float Bs[16][64];
  const float tv = g_ts[stage];
  const int m0 = blockIdx.x*128, tid = threadIdx.x;
  const int lr = tid>>2, lc = (tid&3)<<2;
  const int kr = tid>>4, bc = (tid&15)<<2;
  const int ty = tid>>4, tx = tid&15;
  float* out = g_k[stageOut];

  float acc[8][4];
  #pragma unroll
  for (int i=0;i<8;i++){
    #pragma unroll
    for (int j=0;j<4;j++) acc[i][j]=0.f;
  }

  for (int k0=0;k0<128;k0+=16){
    #pragma unroll
    for (int rr=0;rr<2;rr++){
      int r = lr + rr*64;
      float4 v = ld4(g_h2 + (m0+r)*128 + k0 + lc);
      As[lc+0][r]=v.x; As[lc+1][r]=v.y; As[lc+2][r]=v.z; As[lc+3][r]=v.w;
    }
    st4(&Bs[kr][bc], ld4(w3 + (1+k0+kr)*64 + bc));
    __syncthreads();
    #pragma unroll
    for (int kk=0;kk<16;kk++){
      float4 x0=ld4(&As[kk][ty*8]), x1=ld4(&As[kk][ty*8+4]);
      float4 z0=ld4(&Bs[kk][tx*4]);
      float av[8]={x0.x,x0.y,x0.z,x0.w,x1.x,x1.y,x1.z,x1.w};
      float bv[4]={z0.x,z0.y,z0.z,z0.w};
      #pragma unroll
      for (int i=0;i<8;i++){
        #pragma unroll
        for (int j=0;j<4;j++) acc[i][j]=fmaf(av[i],bv[j],acc[i][j]);
      }
    }
    __syncthreads();
  }
  float be[4];
  #pragma unroll
  for (int j=0;j<4;j++){ int n=tx*4+j; be[j]=b3[n]+tv*w3[n]; }
  #pragma unroll
  for (int i=0;i<8;i++){
    int m=m0+ty*8+i;
    float4 o; o.x=acc[i][0]+be[0]; o.y=acc[i][1]+be[1]; o.z=acc[i][2]+be[2]; o.w=acc[i][3]+be[3];
    st4(out+m*64+tx*4,o);
  }
}

// ---- y5 = y + hs*(B1 k1 + B3 k3 + B4 k4 + B5 k5 + B6 k6) ----
__global__ void k_y5(){
  if (g_done) return;
  const float hs = g_hs;
  int i = blockIdx.x*blockDim.x + threadIdx.x;
  float4 a  = reinterpret_cast<const float4*>(g_y)[i];
  float4 x1 = reinterpret_cast<const float4*>(g_k[0])[i];
  float4 x3 = reinterpret_cast<const float4*>(g_k[2])[i];
  float4 x4 = reinterpret_cast<const float4*>(g_k[3])[i];
  float4 x5 = reinterpret_cast<const float4*>(g_k[4])[i];
  float4 x6 = reinterpret_cast<const float4*>(g_k[5])[i];
  float4 o;
  o.x = a.x + hs*(B1f*x1.x + B3f*x3.x + B4f*x4.x + B5f*x5.x + B6f*x6.x);
  o.y = a.y + hs*(B1f*x1.y + B3f*x3.y + B4f*x4.y + B5f*x5.y + B6f*x6.y);
  o.z = a.z + hs*(B1f*x1.z + B3f*x3.z + B4f*x4.z + B5f*x5.z + B6f*x6.z);
  o.w = a.w + hs*(B1f*x1.w + B3f*x3.w + B4f*x4.w + B5f*x5.w + B6f*x6.w);
  reinterpret_cast<float4*>(g_y5)[i] = o;
}

// ---- error norm partials ----
__global__ void k_errred(){
  __shared__ float sm[256];
  float acc = 0.f;
  if (!g_done){
    const float hs = g_hs;
    for (int i = blockIdx.x*blockDim.x + threadIdx.x; i < NY4; i += gridDim.x*blockDim.x){
      float4 yv = reinterpret_cast<const float4*>(g_y)[i];
      float4 y5 = reinterpret_cast<const float4*>(g_y5)[i];
      float4 x1 = reinterpret_cast<const float4*>(g_k[0])[i];
      float4 x3 = reinterpret_cast<const float4*>(g_k[2])[i];
      float4 x4 = reinterpret_cast<const float4*>(g_k[3])[i];
      float4 x5 = reinterpret_cast<const float4*>(g_k[4])[i];
      float4 x6 = reinterpret_cast<const float4*>(g_k[5])[i];
      float4 x7 = reinterpret_cast<const float4*>(g_k[6])[i];
#define ERRC(c) { \
      float err = hs*(E1f*x1.c + E3f*x3.c + E4f*x4.c + E5f*x5.c + E6f*x6.c + E7f*x7.c); \
      float sc  = 1e-3f + 1e-3f*fmaxf(fabsf(yv.c), fabsf(y5.c)); \
      float r = err/sc; acc += r*r; }
      ERRC(x) ERRC(y) ERRC(z) ERRC(w)
#undef ERRC
    }
  }
  sm[threadIdx.x] = acc; __syncthreads();
  for (int s=128;s>0;s>>=1){ if (threadIdx.x<s) sm[threadIdx.x]+=sm[threadIdx.x+s]; __syncthreads(); }
  if (threadIdx.x==0) g_red[blockIdx.x]=sm[0];
}

__global__ void k_control(){
  __shared__ float sm[512];
  sm[threadIdx.x] = g_red[threadIdx.x]; __syncthreads();
  for (int s=256;s>0;s>>=1){ if (threadIdx.x<s) sm[threadIdx.x]+=sm[threadIdx.x+s]; __syncthreads(); }
  if (threadIdx.x==0){
    if (g_done){ g_accept = 0; return; }
    float en = sqrtf(sm[0] / (float)NYTOT);
    int accept = (en <= 1.0f);
    g_accept = accept;
    if (accept) g_t = g_t + g_hs;
    float en_s = fmaxf(en, 1e-8f);
    float fac = 0.9f * powf(en_s, -0.2f);
    fac = fminf(fmaxf(fac, 0.2f), 10.0f);
    g_h = fmaxf(g_hs * fac, 1e-4f);
  }
}

__global__ void k_commit(){
  if (!g_accept) return;
  int i = blockIdx.x*blockDim.x + threadIdx.x;
  reinterpret_cast<float4*>(g_y)[i] = reinterpret_cast<const float4*>(g_y5)[i];
}

// ---- head: out[m,10] = y[m,:]·wo + bo ----
__global__ void k_head(const float* __restrict__ wo, const float* __restrict__ bo,
                       float* __restrict__ out){
  __shared__ float w[640]; __shared__ float b[10];
  for (int i=threadIdx.x;i<640;i+=256) w[i]=wo[i];
  if (threadIdx.x<10) b[threadIdx.x]=bo[threadIdx.x];
  __syncthreads();
  int m = blockIdx.x*256 + threadIdx.x;
  float acc[10];
  #pragma unroll
  for (int o=0;o<10;o++) acc[o]=b[o];
  for (int c=0;c<64;c++){
    float yv = g_y[m*64+c];
    #pragma unroll
    for (int o=0;o<10;o++) acc[o] = fmaf(yv, w[c*10+o], acc[o]);
  }
  #pragma unroll
  for (int o=0;o<10;o++) out[m*10+o]=acc[o];
}

extern "C" void kernel_launch(void* const* d_in, const int* in_sizes, int n_in,
                              void* d_out, int out_size){
  const float* x  = (const float*)d_in[0];
  const float* w1 = (const float*)d_in[1];
  const float* b1 = (const float*)d_in[2];
  const float* w2 = (const float*)d_in[3];
  const float* b2 = (const float*)d_in[4];
  const float* w3 = (const float*)d_in[5];
  const float* b3 = (const float*)d_in[6];
  const float* wo = (const float*)d_in[7];
  const float* bo = (const float*)d_in[8];
  float* out = (float*)d_out;

  k_init<<<1,1>>>();
  k_copyx<<<2048,256>>>(x);
  k_zero_h1p<<<1024,256>>>();
  for (int it=0; it<32; ++it){
    k_hs<<<1,1>>>();
    for (int s=0; s<6; ++s){
      k_conv1<<<256,256>>>(w1,b1,s,0);
      k_conv2<<<256,256>>>(w2,b2,s);
      k_conv3<<<256,256>>>(w3,b3,s,s);
    }
    k_y5<<<2048,256>>>();
    k_conv1<<<256,256>>>(w1,b1,6,1);
    k_conv2<<<256,256>>>(w2,b2,6);
    k_conv3<<<256,256>>>(w3,b3,6,6);
    k_errred<<<512,256>>>();
    k_control<<<1,512>>>();
    k_commit<<<2048,256>>>();
  }
  k_head<<<128,256>>>(wo,bo,out);
}

// round 4
// speedup vs baseline: 1.0710x; 1.0710x over previous
#include <cuda_runtime.h>
#include <cmath>

#define DINL __device__ __forceinline__
#define NPOS  32768
#define NYTOT 2097152
#define NY4   524288
#define NH1P  4460544
#define NH1P4 1115136

typedef unsigned long long ull;

// ---- device state ----
__device__ float g_ybuf[2][NYTOT];     // ping-pong y / y5
__device__ float g_k[7][NYTOT];
__device__ float g_h1p[NH1P];          // [8][66][66][128] zero-padded
__device__ float g_h2[NPOS*128];
__device__ float g_red[512];
__device__ float g_t, g_h;
__device__ int   g_cur;

// stage tables: cnt, k-indices, coefficients (A rows; stage 6 = 5th-order B weights)
__constant__ int   c_cnt[7]  = {0,1,2,3,4,5,5};
__constant__ int   c_kidx[7][5] = {
  {0,0,0,0,0},{0,0,0,0,0},{0,1,0,0,0},{0,1,2,0,0},{0,1,2,3,0},{0,1,2,3,4},{0,2,3,4,5}};
__constant__ float c_co[7][5] = {
  {0,0,0,0,0},
  {0.2f,0,0,0,0},
  {(float)(3.0/40.0),(float)(9.0/40.0),0,0,0},
  {(float)(44.0/45.0),(float)(-56.0/15.0),(float)(32.0/9.0),0,0},
  {(float)(19372.0/6561.0),(float)(-25360.0/2187.0),(float)(64448.0/6561.0),(float)(-212.0/729.0),0},
  {(float)(9017.0/3168.0),(float)(-355.0/33.0),(float)(46732.0/5247.0),(float)(49.0/176.0),(float)(-5103.0/18656.0)},
  {(float)(35.0/384.0),(float)(500.0/1113.0),(float)(125.0/192.0),(float)(-2187.0/6784.0),(float)(11.0/84.0)}};
__constant__ float c_tf[7] = {0.f,0.2f,0.3f,0.8f,(float)(8.0/9.0),1.f,1.f};

static __device__ __constant__ float E1f=(float)(71.0/57600.0), E3f=(float)(-71.0/16695.0),
  E4f=(float)(71.0/1920.0), E5f=(float)(-17253.0/339200.0), E6f=(float)(22.0/525.0), E7f=(float)(-1.0/40.0);

DINL float4 ld4(const float* p){ return *reinterpret_cast<const float4*>(p); }
DINL void   st4(float* p, float4 v){ *reinterpret_cast<float4*>(p) = v; }
DINL ull pack2(float x){ ull r; asm("mov.b64 %0,{%1,%1};" : "=l"(r) : "f"(x)); return r; }
DINL ull fma2(ull a, ull b, ull c){ ull d; asm("fma.rn.f32x2 %0,%1,%2,%3;" : "=l"(d) : "l"(a),"l"(b),"l"(c)); return d; }
DINL float2 up2(ull v){ float2 f; asm("mov.b64 {%0,%1},%2;" : "=f"(f.x),"=f"(f.y) : "l"(v)); return f; }

// ---- setup ----
__global__ void k_init(){ g_t=0.f; g_h=0.1f; g_cur=0; }

__global__ void k_prep(const float* __restrict__ x){
  int i0 = blockIdx.x*blockDim.x + threadIdx.x, stride = gridDim.x*blockDim.x;
  for (int i=i0;i<NY4;i+=stride)
    reinterpret_cast<float4*>(g_ybuf[0])[i] = reinterpret_cast<const float4*>(x)[i];
  float4 z; z.x=z.y=z.z=z.w=0.f;
  for (int i=i0;i<NH1P4;i+=stride) reinterpret_cast<float4*>(g_h1p)[i] = z;
}

// ---- conv1: [32768,64]x[64,128] + stage combine (+ y5 store on stage6) + time-bias + relu ----
__global__ __launch_bounds__(256) void k_conv1(const float* __restrict__ w1,
                                               const float* __restrict__ b1, int stage){
  float t = g_t, h = g_h;
  if (t >= 1.0f) return;
  float hs = fminf(h, 1.0f - t);
  const float tv = t + hs*c_tf[stage];
  __shared__ float As[16][136];
  __shared__ float Bs[16][128];
  const int cnt = c_cnt[stage];
  float e[5];
  #pragma unroll
  for (int j=0;j<5;j++) e[j] = hs * c_co[stage][j];
  const int cur = g_cur;
  const float* ybase = g_ybuf[cur];
  float* ynext = g_ybuf[cur^1];
  const int m0 = blockIdx.x*128, tid = threadIdx.x;
  const int lr = tid>>2, lc = (tid&3)<<2;
  const int kr = tid>>4, cg = (tid&15)<<3;
  const int ty = tid>>4, tx = tid&15;

  ull acc2[8][4];
  #pragma unroll
  for (int i=0;i<8;i++){
    #pragma unroll
    for (int j=0;j<4;j++) acc2[i][j]=0ull;
  }

  for (int k0=0;k0<64;k0+=16){
    #pragma unroll
    for (int rr=0;rr<2;rr++){
      int r = lr + rr*64;
      int gi = (m0+r)*64 + k0 + lc;
      float4 v = ld4(ybase+gi);
      #pragma unroll
      for (int j=0;j<5;j++){
        if (j < cnt){
          float4 u = ld4(&g_k[c_kidx[stage][j]][gi]);
          v.x=fmaf(e[j],u.x,v.x); v.y=fmaf(e[j],u.y,v.y);
          v.z=fmaf(e[j],u.z,v.z); v.w=fmaf(e[j],u.w,v.w);
        }
      }
      if (stage==6) st4(ynext+gi, v);   // y5 for errred/commit
      As[lc+0][r]=v.x; As[lc+1][r]=v.y; As[lc+2][r]=v.z; As[lc+3][r]=v.w;
    }
    const float* bp = w1 + (1 + k0 + kr)*128 + cg;   // skip time row 0
    st4(&Bs[kr][cg], ld4(bp)); st4(&Bs[kr][cg+4], ld4(bp+4));
    __syncthreads();
    #pragma unroll
    for (int kk=0;kk<16;kk++){
      float4 x0=ld4(&As[kk][ty*8]), x1=ld4(&As[kk][ty*8+4]);
      ulonglong2 zb0 = *reinterpret_cast<const ulonglong2*>(&Bs[kk][tx*8]);
      ulonglong2 zb1 = *reinterpret_cast<const ulonglong2*>(&Bs[kk][tx*8+4]);
      ull bp2[4] = {zb0.x, zb0.y, zb1.x, zb1.y};
      float av[8]={x0.x,x0.y,x0.z,x0.w,x1.x,x1.y,x1.z,x1.w};
      #pragma unroll
      for (int i=0;i<8;i++){
        ull a2 = pack2(av[i]);
        #pragma unroll
        for (int j=0;j<4;j++) acc2[i][j] = fma2(a2, bp2[j], acc2[i][j]);
      }
    }
    __syncthreads();
  }
  float be[8];
  #pragma unroll
  for (int j=0;j<8;j++){ int n=tx*8+j; be[j]=b1[n]+tv*w1[n]; }
  #pragma unroll
  for (int i=0;i<8;i++){
    int m=m0+ty*8+i;
    int bb=m>>12, yy=(m>>6)&63, xx=m&63;
    float* dst = g_h1p + (((bb*66)+(yy+1))*66+(xx+1))*128 + tx*8;
    float2 p0=up2(acc2[i][0]), p1=up2(acc2[i][1]), p2=up2(acc2[i][2]), p3=up2(acc2[i][3]);
    float4 o0,o1;
    o0.x=fmaxf(p0.x+be[0],0.f); o0.y=fmaxf(p0.y+be[1],0.f);
    o0.z=fmaxf(p1.x+be[2],0.f); o0.w=fmaxf(p1.y+be[3],0.f);
    o1.x=fmaxf(p2.x+be[4],0.f); o1.y=fmaxf(p2.y+be[5],0.f);
    o1.z=fmaxf(p3.x+be[6],0.f); o1.w=fmaxf(p3.y+be[7],0.f);
    st4(dst,o0); st4(dst+4,o1);
  }
}

// ---- conv2: implicit 3x3 GEMM [32768,1152]x[1152,128] + time-mask bias + relu ----
__global__ __launch_bounds__(256,2) void k_conv2(const float* __restrict__ w2,
                                                 const float* __restrict__ b2, int stage){
  float t = g_t, h = g_h;
  if (t >= 1.0f) return;
  float hs = fminf(h, 1.0f - t);
  const float tv = t + hs*c_tf[stage];
  __shared__ float As[2][16][136];
  __shared__ float Bs[2][16][128];
  const int m0 = blockIdx.x*128, tid = threadIdx.x;
  const int lr = tid>>2, lc = (tid&3)<<2;
  const int kr = tid>>4, cg = (tid&15)<<3;
  const int ty = tid>>4, tx = tid&15;
  const int bb = m0>>12;
  const int mr0 = m0+lr, mr1 = mr0+64;
  const int base0 = ((bb*66 + (((mr0>>6)&63)+1))*66 + ((mr0&63)+1))*128;
  const int base1 = ((bb*66 + (((mr1>>6)&63)+1))*66 + ((mr1&63)+1))*128;

  ull acc2[8][4];
  #pragma unroll
  for (int i=0;i<8;i++){
    #pragma unroll
    for (int j=0;j<4;j++) acc2[i][j]=0ull;
  }

  float4 a0v,a1v,b0v,b1v;
#define LOADC(KC) { int tap_=(KC)>>3, ci0_=((KC)&7)<<4; \
    int dy_=tap_/3, dx_=tap_-dy_*3; \
    int off_=((dy_-1)*66+(dx_-1))*128 + ci0_ + lc; \
    a0v=ld4(g_h1p+base0+off_); a1v=ld4(g_h1p+base1+off_); \
    const float* bp_=w2+(tap_*129+1+ci0_+kr)*128+cg; \
    b0v=ld4(bp_); b1v=ld4(bp_+4); }
#define STOREC(BUF) { \
    As[BUF][lc+0][lr]=a0v.x; As[BUF][lc+1][lr]=a0v.y; As[BUF][lc+2][lr]=a0v.z; As[BUF][lc+3][lr]=a0v.w; \
    As[BUF][lc+0][lr+64]=a1v.x; As[BUF][lc+1][lr+64]=a1v.y; As[BUF][lc+2][lr+64]=a1v.z; As[BUF][lc+3][lr+64]=a1v.w; \
    st4(&Bs[BUF][kr][cg],b0v); st4(&Bs[BUF][kr][cg+4],b1v); }

  LOADC(0); STOREC(0); __syncthreads();
  for (int kc=0;kc<72;kc++){
    int cur = kc&1;
    if (kc<71) LOADC(kc+1);
    #pragma unroll
    for (int kk=0;kk<16;kk++){
      float4 x0=ld4(&As[cur][kk][ty*8]), x1=ld4(&As[cur][kk][ty*8+4]);
      ulonglong2 zb0 = *reinterpret_cast<const ulonglong2*>(&Bs[cur][kk][tx*8]);
      ulonglong2 zb1 = *reinterpret_cast<const ulonglong2*>(&Bs[cur][kk][tx*8+4]);
      ull bp2[4] = {zb0.x, zb0.y, zb1.x, zb1.y};
      float av[8]={x0.x,x0.y,x0.z,x0.w,x1.x,x1.y,x1.z,x1.w};
      #pragma unroll
      for (int i=0;i<8;i++){
        ull a2 = pack2(av[i]);
        #pragma unroll
        for (int j=0;j<4;j++) acc2[i][j] = fma2(a2, bp2[j], acc2[i][j]);
      }
    }
    __syncthreads();
    if (kc<71){ STOREC((kc&1)^1); __syncthreads(); }
  }
#undef LOADC
#undef STOREC
  // epilogue: time-row of each tap, with border validity mask
  float* w2ts = &As[0][0][0];             // 1152 floats
  for (int i=tid;i<1152;i+=256){ int tap=i>>7, f=i&127; w2ts[i]=w2[(tap*129)*128+f]; }
  __syncthreads();
  float be[8];
  #pragma unroll
  for (int j=0;j<8;j++) be[j]=b2[tx*8+j];
  #pragma unroll
  for (int i=0;i<8;i++){
    int m=m0+ty*8+i;
    int yy=(m>>6)&63, xx=m&63;
    float tb[8]={0,0,0,0,0,0,0,0};
    #pragma unroll
    for (int tyy=0;tyy<3;tyy++){
      bool vy = (tyy==0)?(yy>0):((tyy==2)?(yy<63):true);
      #pragma unroll
      for (int txx=0;txx<3;txx++){
        bool vx = (txx==0)?(xx>0):((txx==2)?(xx<63):true);
        if (vy&&vx){
          int tap=tyy*3+txx;
          #pragma unroll
          for (int j=0;j<8;j++) tb[j]+=w2ts[tap*128+tx*8+j];
        }
      }
    }
    float2 p0=up2(acc2[i][0]), p1=up2(acc2[i][1]), p2=up2(acc2[i][2]), p3=up2(acc2[i][3]);
    float4 o0,o1;
    o0.x=fmaxf(p0.x+be[0]+tv*tb[0],0.f); o0.y=fmaxf(p0.y+be[1]+tv*tb[1],0.f);
    o0.z=fmaxf(p1.x+be[2]+tv*tb[2],0.f); o0.w=fmaxf(p1.y+be[3]+tv*tb[3],0.f);
    o1.x=fmaxf(p2.x+be[4]+tv*tb[4],0.f); o1.y=fmaxf(p2.y+be[5]+tv*tb[5],0.f);
    o1.z=fmaxf(p3.x+be[6]+tv*tb[6],0.f); o1.w=fmaxf(p3.y+be[7]+tv*tb[7],0.f);
    st4(g_h2+m*128+tx*8,o0); st4(g_h2+m*128+tx*8+4,o1);
  }
}

// ---- conv3: [32768,128]x[128,64] + time-bias -> g_k[stage] ----
__global__ __launch_bounds__(256) void k_conv3(const float* __restrict__ w3,
                                               const float* __restrict__ b3, int stage){
  float t = g_t, h = g_h;
  if (t >= 1.0f) return;
  float hs = fminf(h, 1.0f - t);
  const float tv = t + hs*c_tf[stage];
  __shared__ float As[16][136];
  __shared__ float Bs[16][64];
  const int m0 = blockIdx.x*128, tid = threadIdx.x;
  const int lr = tid>>2, lc = (tid&3)<<2;
  const int kr = tid>>4, bc = (tid&15)<<2;
  const int ty = tid>>4, tx = tid&15;
  float* out = g_k[stage];

  ull acc2[8][2];
  #pragma unroll
  for (int i=0;i<8;i++){ acc2[i][0]=0ull; acc2[i][1]=0ull; }

  for (int k0=0;k0<128;k0+=16){
    #pragma unroll
    for (int rr=0;rr<2;rr++){
      int r = lr + rr*64;
      float4 v = ld4(g_h2 + (m0+r)*128 + k0 + lc);
      As[lc+0][r]=v.x; As[lc+1][r]=v.y; As[lc+2][r]=v.z; As[lc+3][r]=v.w;
    }
    st4(&Bs[kr][bc], ld4(w3 + (1+k0+kr)*64 + bc));
    __syncthreads();
    #pragma unroll
    for (int kk=0;kk<16;kk++){
      float4 x0=ld4(&As[kk][ty*8]), x1=ld4(&As[kk][ty*8+4]);
      ulonglong2 zb = *reinterpret_cast<const ulonglong2*>(&Bs[kk][tx*4]);
      float av[8]={x0.x,x0.y,x0.z,x0.w,x1.x,x1.y,x1.z,x1.w};
      #pragma unroll
      for (int i=0;i<8;i++){
        ull a2 = pack2(av[i]);
        acc2[i][0] = fma2(a2, zb.x, acc2[i][0]);
        acc2[i][1] = fma2(a2, zb.y, acc2[i][1]);
      }
    }
    __syncthreads();
  }
  float be[4];
  #pragma unroll
  for (int j=0;j<4;j++){ int n=tx*4+j; be[j]=b3[n]+tv*w3[n]; }
  #pragma unroll
  for (int i=0;i<8;i++){
    int m=m0+ty*8+i;
    float2 p0=up2(acc2[i][0]), p1=up2(acc2[i][1]);
    float4 o; o.x=p0.x+be[0]; o.y=p0.y+be[1]; o.z=p1.x+be[2]; o.w=p1.y+be[3];
    st4(out+m*64+tx*4,o);
  }
}

// ---- error norm partials (y = cur buffer, y5 = other buffer) ----
__global__ void k_errred(){
  __shared__ float sm[256];
  float acc = 0.f;
  float t = g_t, h = g_h;
  if (t < 1.0f){
    const float hs = fminf(h, 1.0f - t);
    const int cur = g_cur;
    const float* yb  = g_ybuf[cur];
    const float* y5b = g_ybuf[cur^1];
    for (int i = blockIdx.x*blockDim.x + threadIdx.x; i < NY4; i += gridDim.x*blockDim.x){
      float4 yv = reinterpret_cast<const float4*>(yb)[i];
      float4 y5 = reinterpret_cast<const float4*>(y5b)[i];
      float4 x1 = reinterpret_cast<const float4*>(g_k[0])[i];
      float4 x3 = reinterpret_cast<const float4*>(g_k[2])[i];
      float4 x4 = reinterpret_cast<const float4*>(g_k[3])[i];
      float4 x5 = reinterpret_cast<const float4*>(g_k[4])[i];
      float4 x6 = reinterpret_cast<const float4*>(g_k[5])[i];
      float4 x7 = reinterpret_cast<const float4*>(g_k[6])[i];
#define ERRC(c) { \
      float err = hs*(E1f*x1.c + E3f*x3.c + E4f*x4.c + E5f*x5.c + E6f*x6.c + E7f*x7.c); \
      float sc  = 1e-3f + 1e-3f*fmaxf(fabsf(yv.c), fabsf(y5.c)); \
      float r = err/sc; acc += r*r; }
      ERRC(x) ERRC(y) ERRC(z) ERRC(w)
#undef ERRC
    }
  }
  sm[threadIdx.x] = acc; __syncthreads();
  for (int s=128;s>0;s>>=1){ if (threadIdx.x<s) sm[threadIdx.x]+=sm[threadIdx.x+s]; __syncthreads(); }
  if (threadIdx.x==0) g_red[blockIdx.x]=sm[0];
}

__global__ void k_control(){
  __shared__ float sm[512];
  sm[threadIdx.x] = g_red[threadIdx.x]; __syncthreads();
  for (int s=256;s>0;s>>=1){ if (threadIdx.x<s) sm[threadIdx.x]+=sm[threadIdx.x+s]; __syncthreads(); }
  if (threadIdx.x==0){
    float t = g_t;
    if (t >= 1.0f) return;
    float hs = fminf(g_h, 1.0f - t);
    float en = sqrtf(sm[0] / (float)NYTOT);
    if (en <= 1.0f){ g_t = t + hs; g_cur ^= 1; }   // accept: flip to y5 buffer
    float en_s = fmaxf(en, 1e-8f);
    float fac = 0.9f * powf(en_s, -0.2f);
    fac = fminf(fmaxf(fac, 0.2f), 10.0f);
    g_h = fmaxf(hs * fac, 1e-4f);
  }
}

// ---- head: out[m,10] = y[m,:]·wo + bo ----
__global__ void k_head(const float* __restrict__ wo, const float* __restrict__ bo,
                       float* __restrict__ out){
  __shared__ float w[640]; __shared__ float b[10];
  for (int i=threadIdx.x;i<640;i+=256) w[i]=wo[i];
  if (threadIdx.x<10) b[threadIdx.x]=bo[threadIdx.x];
  __syncthreads();
  const float* y = g_ybuf[g_cur];
  int m = blockIdx.x*256 + threadIdx.x;
  float acc[10];
  #pragma unroll
  for (int o=0;o<10;o++) acc[o]=b[o];
  for (int c=0;c<64;c++){
    float yv = y[m*64+c];
    #pragma unroll
    for (int o=0;o<10;o++) acc[o] = fmaf(yv, w[c*10+o], acc[o]);
  }
  #pragma unroll
  for (int o=0;o<10;o++) out[m*10+o]=acc[o];
}

extern "C" void kernel_launch(void* const* d_in, const int* in_sizes, int n_in,
                              void* d_out, int out_size){
  const float* x  = (const float*)d_in[0];
  const float* w1 = (const float*)d_in[1];
  const float* b1 = (const float*)d_in[2];
  const float* w2 = (const float*)d_in[3];
  const float* b2 = (const float*)d_in[4];
  const float* w3 = (const float*)d_in[5];
  const float* b3 = (const float*)d_in[6];
  const float* wo = (const float*)d_in[7];
  const float* bo = (const float*)d_in[8];
  float* out = (float*)d_out;

  k_init<<<1,1>>>();          // our idx0
  k_prep<<<2048,256>>>(x);    // our idx1
  for (int it=0; it<32; ++it){
    for (int s=0; s<7; ++s){
      k_conv1<<<256,256>>>(w1,b1,s);   // iter0 s0: our idx2 (global 4)
      k_conv2<<<256,256>>>(w2,b2,s);   // iter0 s0: our idx3 (global 5) <- ncu target
      k_conv3<<<256,256>>>(w3,b3,s);
    }
    k_errred<<<512,256>>>();
    k_control<<<1,512>>>();
  }
  k_head<<<128,256>>>(wo,bo,out);
}

// round 5
// speedup vs baseline: 1.1012x; 1.0282x over previous
#include <cuda_runtime.h>
#include <cmath>

#define DINL __device__ __forceinline__
#define NPOS  32768
#define NYTOT 2097152
#define NY4   524288
#define NH1P  4460544
#define NH1P4 1115136

typedef unsigned long long ull;

// ---- device state ----
__device__ float g_ybuf[2][NYTOT];     // ping-pong y / y5
__device__ float g_k[7][NYTOT];
__device__ float g_h1p[NH1P];          // [8][66][66][128] zero-padded
__device__ float g_red[512];
__device__ float g_t, g_h;
__device__ int   g_cur;
__device__ unsigned int g_ctr;

// stage tables
__constant__ int   c_cnt[7]  = {0,1,2,3,4,5,5};
__constant__ int   c_kidx[7][5] = {
  {0,0,0,0,0},{0,0,0,0,0},{0,1,0,0,0},{0,1,2,0,0},{0,1,2,3,0},{0,1,2,3,4},{0,2,3,4,5}};
__constant__ float c_co[7][5] = {
  {0,0,0,0,0},
  {0.2f,0,0,0,0},
  {(float)(3.0/40.0),(float)(9.0/40.0),0,0,0},
  {(float)(44.0/45.0),(float)(-56.0/15.0),(float)(32.0/9.0),0,0},
  {(float)(19372.0/6561.0),(float)(-25360.0/2187.0),(float)(64448.0/6561.0),(float)(-212.0/729.0),0},
  {(float)(9017.0/3168.0),(float)(-355.0/33.0),(float)(46732.0/5247.0),(float)(49.0/176.0),(float)(-5103.0/18656.0)},
  {(float)(35.0/384.0),(float)(500.0/1113.0),(float)(125.0/192.0),(float)(-2187.0/6784.0),(float)(11.0/84.0)}};
__constant__ float c_tf[7] = {0.f,0.2f,0.3f,0.8f,(float)(8.0/9.0),1.f,1.f};

static __device__ __constant__ float E1f=(float)(71.0/57600.0), E3f=(float)(-71.0/16695.0),
  E4f=(float)(71.0/1920.0), E5f=(float)(-17253.0/339200.0), E6f=(float)(22.0/525.0), E7f=(float)(-1.0/40.0);

DINL float4 ld4(const float* p){ return *reinterpret_cast<const float4*>(p); }
DINL void   st4(float* p, float4 v){ *reinterpret_cast<float4*>(p) = v; }
DINL ull pack2(float x){ ull r; asm("mov.b64 %0,{%1,%1};" : "=l"(r) : "f"(x)); return r; }
DINL ull fma2(ull a, ull b, ull c){ ull d; asm("fma.rn.f32x2 %0,%1,%2,%3;" : "=l"(d) : "l"(a),"l"(b),"l"(c)); return d; }
DINL float2 up2(ull v){ float2 f; asm("mov.b64 {%0,%1},%2;" : "=f"(f.x),"=f"(f.y) : "l"(v)); return f; }

// ---- setup ----
__global__ void k_init(){ g_t=0.f; g_h=0.1f; g_cur=0; g_ctr=0u; }

__global__ void k_prep(const float* __restrict__ x){
  int i0 = blockIdx.x*blockDim.x + threadIdx.x, stride = gridDim.x*blockDim.x;
  for (int i=i0;i<NY4;i+=stride)
    reinterpret_cast<float4*>(g_ybuf[0])[i] = reinterpret_cast<const float4*>(x)[i];
  float4 z; z.x=z.y=z.z=z.w=0.f;
  for (int i=i0;i<NH1P4;i+=stride) reinterpret_cast<float4*>(g_h1p)[i] = z;
}

// ---- conv1: [32768,64]x[64,128] + stage combine (+ y5 store on stage6) + time-bias + relu ----
__global__ __launch_bounds__(256) void k_conv1(const float* __restrict__ w1,
                                               const float* __restrict__ b1, int stage){
  float t = g_t, h = g_h;
  if (t >= 1.0f) return;
  float hs = fminf(h, 1.0f - t);
  const float tv = t + hs*c_tf[stage];
  __shared__ float As[16][136];
  __shared__ float Bs[16][128];
  const int cnt = c_cnt[stage];
  float e[5];
  #pragma unroll
  for (int j=0;j<5;j++) e[j] = hs * c_co[stage][j];
  const int cur = g_cur;
  const float* ybase = g_ybuf[cur];
  float* ynext = g_ybuf[cur^1];
  const int m0 = blockIdx.x*128, tid = threadIdx.x;
  const int lr = tid>>2, lc = (tid&3)<<2;
  const int kr = tid>>4, cg = (tid&15)<<3;
  const int ty = tid>>4, tx = tid&15;

  ull acc2[8][4];
  #pragma unroll
  for (int i=0;i<8;i++){
    #pragma unroll
    for (int j=0;j<4;j++) acc2[i][j]=0ull;
  }

  for (int k0=0;k0<64;k0+=16){
    #pragma unroll
    for (int rr=0;rr<2;rr++){
      int r = lr + rr*64;
      int gi = (m0+r)*64 + k0 + lc;
      float4 v = ld4(ybase+gi);
      #pragma unroll
      for (int j=0;j<5;j++){
        if (j < cnt){
          float4 u = ld4(&g_k[c_kidx[stage][j]][gi]);
          v.x=fmaf(e[j],u.x,v.x); v.y=fmaf(e[j],u.y,v.y);
          v.z=fmaf(e[j],u.z,v.z); v.w=fmaf(e[j],u.w,v.w);
        }
      }
      if (stage==6) st4(ynext+gi, v);   // y5 for errctl/commit
      As[lc+0][r]=v.x; As[lc+1][r]=v.y; As[lc+2][r]=v.z; As[lc+3][r]=v.w;
    }
    const float* bp = w1 + (1 + k0 + kr)*128 + cg;   // skip time row 0
    st4(&Bs[kr][cg], ld4(bp)); st4(&Bs[kr][cg+4], ld4(bp+4));
    __syncthreads();
    #pragma unroll
    for (int kk=0;kk<16;kk++){
      float4 x0=ld4(&As[kk][ty*8]), x1=ld4(&As[kk][ty*8+4]);
      ulonglong2 zb0 = *reinterpret_cast<const ulonglong2*>(&Bs[kk][tx*8]);
      ulonglong2 zb1 = *reinterpret_cast<const ulonglong2*>(&Bs[kk][tx*8+4]);
      ull bp2[4] = {zb0.x, zb0.y, zb1.x, zb1.y};
      float av[8]={x0.x,x0.y,x0.z,x0.w,x1.x,x1.y,x1.z,x1.w};
      #pragma unroll
      for (int i=0;i<8;i++){
        ull a2 = pack2(av[i]);
        #pragma unroll
        for (int j=0;j<4;j++) acc2[i][j] = fma2(a2, bp2[j], acc2[i][j]);
      }
    }
    __syncthreads();
  }
  float be[8];
  #pragma unroll
  for (int j=0;j<8;j++){ int n=tx*8+j; be[j]=b1[n]+tv*w1[n]; }
  #pragma unroll
  for (int i=0;i<8;i++){
    int m=m0+ty*8+i;
    int bb=m>>12, yy=(m>>6)&63, xx=m&63;
    float* dst = g_h1p + (((bb*66)+(yy+1))*66+(xx+1))*128 + tx*8;
    float2 p0=up2(acc2[i][0]), p1=up2(acc2[i][1]), p2=up2(acc2[i][2]), p3=up2(acc2[i][3]);
    float4 o0,o1;
    o0.x=fmaxf(p0.x+be[0],0.f); o0.y=fmaxf(p0.y+be[1],0.f);
    o0.z=fmaxf(p1.x+be[2],0.f); o0.w=fmaxf(p1.y+be[3],0.f);
    o1.x=fmaxf(p2.x+be[4],0.f); o1.y=fmaxf(p2.y+be[5],0.f);
    o1.z=fmaxf(p3.x+be[6],0.f); o1.w=fmaxf(p3.y+be[7],0.f);
    st4(dst,o0); st4(dst+4,o1);
  }
}

// ---- conv23: implicit 3x3 GEMM + relu -> smem h2 (transposed) -> GEMM x w3 -> g_k[stage] ----
// dynamic smem layout (floats):
//   As2: [2][16][136]  = 4352    (also reused as w2ts[1152] and Bs3[16][68]=1088)
//   Bs2: [2][16][128]  = 4096
//   h2s: [128][136]    = 17408   (h2s[c][m], transposed for phase-2 broadcast reads)
#define CONV23_SMEM_FLOATS (4352+4096+17408)
__global__ __launch_bounds__(256,2) void k_conv23(const float* __restrict__ w2,
                                                  const float* __restrict__ b2,
                                                  const float* __restrict__ w3,
                                                  const float* __restrict__ b3, int stage){
  float t = g_t, h = g_h;
  if (t >= 1.0f) return;
  float hs = fminf(h, 1.0f - t);
  const float tv = t + hs*c_tf[stage];
  extern __shared__ float dynsm[];
  float* As2 = dynsm;                 // [2][16][136]
  float* Bs2 = dynsm + 4352;          // [2][16][128]
  float* h2s = dynsm + 8448;          // [128][136]
#define AS2(b,k,r) As2[(b)*2176 + (k)*136 + (r)]
#define BS2(b,k,c) Bs2[(b)*2048 + (k)*128 + (c)]
  const int m0 = blockIdx.x*128, tid = threadIdx.x;
  const int lr = tid>>2, lc = (tid&3)<<2;
  const int kr = tid>>4, cg = (tid&15)<<3;
  const int ty = tid>>4, tx = tid&15;
  const int bb = m0>>12;
  const int mr0 = m0+lr, mr1 = mr0+64;
  const int base0 = ((bb*66 + (((mr0>>6)&63)+1))*66 + ((mr0&63)+1))*128;
  const int base1 = ((bb*66 + (((mr1>>6)&63)+1))*66 + ((mr1&63)+1))*128;

  ull acc2[8][4];
  #pragma unroll
  for (int i=0;i<8;i++){
    #pragma unroll
    for (int j=0;j<4;j++) acc2[i][j]=0ull;
  }

  float4 a0v,a1v,b0v,b1v;
#define LOADC(KC) { int tap_=(KC)>>3, ci0_=((KC)&7)<<4; \
    int dy_=tap_/3, dx_=tap_-dy_*3; \
    int off_=((dy_-1)*66+(dx_-1))*128 + ci0_ + lc; \
    a0v=ld4(g_h1p+base0+off_); a1v=ld4(g_h1p+base1+off_); \
    const float* bp_=w2+(tap_*129+1+ci0_+kr)*128+cg; \
    b0v=ld4(bp_); b1v=ld4(bp_+4); }
#define STOREC(BUF) { \
    AS2(BUF,lc+0,lr)=a0v.x; AS2(BUF,lc+1,lr)=a0v.y; AS2(BUF,lc+2,lr)=a0v.z; AS2(BUF,lc+3,lr)=a0v.w; \
    AS2(BUF,lc+0,lr+64)=a1v.x; AS2(BUF,lc+1,lr+64)=a1v.y; AS2(BUF,lc+2,lr+64)=a1v.z; AS2(BUF,lc+3,lr+64)=a1v.w; \
    st4(&BS2(BUF,kr,cg),b0v); st4(&BS2(BUF,kr,cg+4),b1v); }

  LOADC(0); STOREC(0); __syncthreads();
  for (int kc=0;kc<72;kc++){
    int cur = kc&1;
    if (kc<71) LOADC(kc+1);
    #pragma unroll
    for (int kk=0;kk<16;kk++){
      float4 x0=ld4(&AS2(cur,kk,ty*8)), x1=ld4(&AS2(cur,kk,ty*8+4));
      ulonglong2 zb0 = *reinterpret_cast<const ulonglong2*>(&BS2(cur,kk,tx*8));
      ulonglong2 zb1 = *reinterpret_cast<const ulonglong2*>(&BS2(cur,kk,tx*8+4));
      ull bp2[4] = {zb0.x, zb0.y, zb1.x, zb1.y};
      float av[8]={x0.x,x0.y,x0.z,x0.w,x1.x,x1.y,x1.z,x1.w};
      #pragma unroll
      for (int i=0;i<8;i++){
        ull a2 = pack2(av[i]);
        #pragma unroll
        for (int j=0;j<4;j++) acc2[i][j] = fma2(a2, bp2[j], acc2[i][j]);
      }
    }
    __syncthreads();
    if (kc<71){ STOREC((kc&1)^1); __syncthreads(); }
  }
#undef LOADC
#undef STOREC

  // ---- phase-1 epilogue: time-row bias (border masked) + relu -> h2s[c][m] ----
  float* w2ts = As2;                       // 1152 floats, reuse
  for (int i=tid;i<1152;i+=256){ int tap=i>>7, f=i&127; w2ts[i]=w2[(tap*129)*128+f]; }
  __syncthreads();
  {
    float be[8];
    #pragma unroll
    for (int j=0;j<8;j++) be[j]=b2[tx*8+j];
    #pragma unroll
    for (int i=0;i<8;i++){
      int m=m0+ty*8+i;
      int yy=(m>>6)&63, xx=m&63;
      float tb[8]={0,0,0,0,0,0,0,0};
      #pragma unroll
      for (int tyy=0;tyy<3;tyy++){
        bool vy = (tyy==0)?(yy>0):((tyy==2)?(yy<63):true);
        #pragma unroll
        for (int txx=0;txx<3;txx++){
          bool vx = (txx==0)?(xx>0):((txx==2)?(xx<63):true);
          if (vy&&vx){
            int tap=tyy*3+txx;
            #pragma unroll
            for (int j=0;j<8;j++) tb[j]+=w2ts[tap*128+tx*8+j];
          }
        }
      }
      float2 p[4] = {up2(acc2[i][0]),up2(acc2[i][1]),up2(acc2[i][2]),up2(acc2[i][3])};
      float ov[8] = {p[0].x,p[0].y,p[1].x,p[1].y,p[2].x,p[2].y,p[3].x,p[3].y};
      #pragma unroll
      for (int j=0;j<8;j++){
        float v = fmaxf(ov[j]+be[j]+tv*tb[j], 0.f);
        h2s[(tx*8+j)*136 + ty*8+i] = v;      // transposed store (one-time)
      }
    }
  }
  __syncthreads();

  // ---- phase 2: k = h2[128x128] x w3[128x64] + time-bias -> g_k[stage] ----
  float* Bs3 = As2;                        // [16][68], reuse
  const int bc = (tid&15)<<2;
  ull acc3[8][2];
  #pragma unroll
  for (int i=0;i<8;i++){ acc3[i][0]=0ull; acc3[i][1]=0ull; }
  for (int c0=0;c0<128;c0+=16){
    st4(&Bs3[kr*68 + bc], ld4(w3 + (1+c0+kr)*64 + bc));
    __syncthreads();
    #pragma unroll
    for (int kk=0;kk<16;kk++){
      float4 x0=ld4(&h2s[(c0+kk)*136 + ty*8]), x1=ld4(&h2s[(c0+kk)*136 + ty*8+4]);
      ulonglong2 zb = *reinterpret_cast<const ulonglong2*>(&Bs3[kk*68 + tx*4]);
      float av[8]={x0.x,x0.y,x0.z,x0.w,x1.x,x1.y,x1.z,x1.w};
      #pragma unroll
      for (int i=0;i<8;i++){
        ull a2 = pack2(av[i]);
        acc3[i][0] = fma2(a2, zb.x, acc3[i][0]);
        acc3[i][1] = fma2(a2, zb.y, acc3[i][1]);
      }
    }
    __syncthreads();
  }
  float* out = g_k[stage];
  float be3[4];
  #pragma unroll
  for (int j=0;j<4;j++){ int n=tx*4+j; be3[j]=b3[n]+tv*w3[n]; }
  #pragma unroll
  for (int i=0;i<8;i++){
    int m=m0+ty*8+i;
    float2 p0=up2(acc3[i][0]), p1=up2(acc3[i][1]);
    float4 o; o.x=p0.x+be3[0]; o.y=p0.y+be3[1]; o.z=p1.x+be3[2]; o.w=p1.y+be3[3];
    st4(out+m*64+tx*4,o);
  }
#undef AS2
#undef BS2
}

// ---- fused error norm + step control (last-block pattern) ----
__global__ void k_errctl(){
  __shared__ float sm[256];
  __shared__ bool amLast;
  float acc = 0.f;
  float t = g_t, h = g_h;
  const float hs = fminf(h, 1.0f - t);
  if (t < 1.0f){
    const int cur = g_cur;
    const float* yb  = g_ybuf[cur];
    const float* y5b = g_ybuf[cur^1];
    for (int i = blockIdx.x*blockDim.x + threadIdx.x; i < NY4; i += gridDim.x*blockDim.x){
      float4 yv = reinterpret_cast<const float4*>(yb)[i];
      float4 y5 = reinterpret_cast<const float4*>(y5b)[i];
      float4 x1 = reinterpret_cast<const float4*>(g_k[0])[i];
      float4 x3 = reinterpret_cast<const float4*>(g_k[2])[i];
      float4 x4 = reinterpret_cast<const float4*>(g_k[3])[i];
      float4 x5 = reinterpret_cast<const float4*>(g_k[4])[i];
      float4 x6 = reinterpret_cast<const float4*>(g_k[5])[i];
      float4 x7 = reinterpret_cast<const float4*>(g_k[6])[i];
#define ERRC(c) { \
      float err = hs*(E1f*x1.c + E3f*x3.c + E4f*x4.c + E5f*x5.c + E6f*x6.c + E7f*x7.c); \
      float sc  = 1e-3f + 1e-3f*fmaxf(fabsf(yv.c), fabsf(y5.c)); \
      float r = err/sc; acc += r*r; }
      ERRC(x) ERRC(y) ERRC(z) ERRC(w)
#undef ERRC
    }
  }
  sm[threadIdx.x] = acc; __syncthreads();
  for (int s=128;s>0;s>>=1){ if (threadIdx.x<s) sm[threadIdx.x]+=sm[threadIdx.x+s]; __syncthreads(); }
  if (threadIdx.x==0){
    g_red[blockIdx.x]=sm[0];
    __threadfence();
    unsigned int prev = atomicAdd(&g_ctr, 1u);
    amLast = (prev == gridDim.x - 1u);
  }
  __syncthreads();
  if (amLast){
    __threadfence();
    sm[threadIdx.x] = g_red[threadIdx.x] + g_red[threadIdx.x+256];
    __syncthreads();
    for (int s=128;s>0;s>>=1){ if (threadIdx.x<s) sm[threadIdx.x]+=sm[threadIdx.x+s]; __syncthreads(); }
    if (threadIdx.x==0){
      g_ctr = 0u;
      if (t < 1.0f){
        float en = sqrtf(sm[0] / (float)NYTOT);
        if (en <= 1.0f){ g_t = t + hs; g_cur ^= 1; }
        float en_s = fmaxf(en, 1e-8f);
        float fac = 0.9f * powf(en_s, -0.2f);
        fac = fminf(fmaxf(fac, 0.2f), 10.0f);
        g_h = fmaxf(hs * fac, 1e-4f);
      }
    }
  }
}

// ---- head: out[m,10] = y[m,:]·wo + bo ----
__global__ void k_head(const float* __restrict__ wo, const float* __restrict__ bo,
                       float* __restrict__ out){
  __shared__ float w[640]; __shared__ float b[10];
  for (int i=threadIdx.x;i<640;i+=256) w[i]=wo[i];
  if (threadIdx.x<10) b[threadIdx.x]=bo[threadIdx.x];
  __syncthreads();
  const float* y = g_ybuf[g_cur];
  int m = blockIdx.x*256 + threadIdx.x;
  float acc[10];
  #pragma unroll
  for (int o=0;o<10;o++) acc[o]=b[o];
  for (int c=0;c<64;c++){
    float yv = y[m*64+c];
    #pragma unroll
    for (int o=0;o<10;o++) acc[o] = fmaf(yv, w[c*10+o], acc[o]);
  }
  #pragma unroll
  for (int o=0;o<10;o++) out[m*10+o]=acc[o];
}

extern "C" void kernel_launch(void* const* d_in, const int* in_sizes, int n_in,
                              void* d_out, int out_size){
  const float* x  = (const float*)d_in[0];
  const float* w1 = (const float*)d_in[1];
  const float* b1 = (const float*)d_in[2];
  const float* w2 = (const float*)d_in[3];
  const float* b2 = (const float*)d_in[4];
  const float* w3 = (const float*)d_in[5];
  const float* b3 = (const float*)d_in[6];
  const float* wo = (const float*)d_in[7];
  const float* bo = (const float*)d_in[8];
  float* out = (float*)d_out;
  const int smem23 = CONV23_SMEM_FLOATS * 4;   // 103424 B

  static int attrSet = 0;
  if (!attrSet){
    cudaFuncSetAttribute(k_conv23, cudaFuncAttributeMaxDynamicSharedMemorySize, smem23);
    attrSet = 1;
  }

  k_init<<<1,1>>>();          // our idx0
  k_prep<<<2048,256>>>(x);    // our idx1
  for (int it=0; it<32; ++it){
    for (int s=0; s<7; ++s){
      k_conv1 <<<256,256>>>(w1,b1,s);                 // iter0 s0: global idx 4
      k_conv23<<<256,256,smem23>>>(w2,b2,w3,b3,s);    // iter0 s0: global idx 5 <- ncu
    }
    k_errctl<<<512,256>>>();
  }
  k_head<<<128,256>>>(wo,bo,out);
}